// round 3
// baseline (speedup 1.0000x reference)
#include <cuda_runtime.h>
#include <cuda_bf16.h>
#include <float.h>

// DimensionAdaptivePoolingForSensors:
//   x: (B=64, w=512, h=48, M=64) f32  ->  out: (B=64, 16*6*64) f32
// Bins are exactly uniform: w-bin = w/32 (16 bins), h-bin = h/8 (6 bins).
// out[b, iw*384 + ih*64 + m] = max over w in [iw*32,iw*32+32), h in [ih*8,ih*8+8) of x[b,w,h,m]
//
// Strategy: one block per (iw, b). The w-stride equals the (h,m) plane size,
// so each block streams a fully contiguous 384 KB region of x exactly once.
// 768 threads: thread t owns (h = t>>4, mvec = t&15) as a float4 accumulator;
// a warp reads 512 contiguous bytes per w-row -> perfect LDG.128 coalescing.
// Then an 8:1 smem reduction over h within each h-bin produces the output.

#define POOL_W 16
#define POOL_H 6
#define DIM_B  64
#define DIM_W  512
#define DIM_H  48
#define DIM_M  64
#define WIN_W  32   // DIM_W / POOL_W
#define WIN_H  8    // DIM_H / POOL_H
#define MV     (DIM_M / 4)        // 16 float4 per (b,w,h) row
#define THREADS (DIM_H * MV)      // 48 * 16 = 768

__device__ __forceinline__ float4 f4max(float4 a, float4 b) {
    return make_float4(fmaxf(a.x, b.x), fmaxf(a.y, b.y),
                       fmaxf(a.z, b.z), fmaxf(a.w, b.w));
}

__global__ __launch_bounds__(THREADS, 2)
void dap_pool_kernel(const float4* __restrict__ x4, float4* __restrict__ out4) {
    const int iw = blockIdx.x;   // 0..15
    const int b  = blockIdx.y;   // 0..63
    const int t  = threadIdx.x;  // 0..767
    const int mv = t & (MV - 1); // 0..15
    const int h  = t >> 4;       // 0..47

    // float4-unit index: b*512*48*16 + w*48*16 + h*16 + mv ; w = iw*32 + wl
    const float4* base = x4
        + (size_t)b * (DIM_W * DIM_H * MV)
        + (size_t)(iw * WIN_W) * (DIM_H * MV)
        + (size_t)h * MV + mv;

    float4 acc = make_float4(-FLT_MAX, -FLT_MAX, -FLT_MAX, -FLT_MAX);
    #pragma unroll 8
    for (int wl = 0; wl < WIN_W; ++wl) {
        acc = f4max(acc, base[(size_t)wl * (DIM_H * MV)]);
    }

    __shared__ float4 smem[THREADS];  // [h][mv], 12 KB
    smem[t] = acc;
    __syncthreads();

    // 96 threads: (ih = 0..5, mv = 0..15) reduce 8 h-rows and write output.
    if (t < POOL_H * MV) {
        const int ih = t >> 4;
        const int m  = t & (MV - 1);
        float4 r = smem[(ih * WIN_H) * MV + m];
        #pragma unroll
        for (int j = 1; j < WIN_H; ++j)
            r = f4max(r, smem[(ih * WIN_H + j) * MV + m]);
        // out float4 index: b*1536 + iw*96 + ih*16 + m
        out4[(size_t)b * (POOL_W * POOL_H * MV)
             + (size_t)iw * (POOL_H * MV)
             + (size_t)ih * MV + m] = r;
    }
}

extern "C" void kernel_launch(void* const* d_in, const int* in_sizes, int n_in,
                              void* d_out, int out_size) {
    const float4* x4  = (const float4*)d_in[0];
    float4*      out4 = (float4*)d_out;
    dim3 grid(POOL_W, DIM_B);
    dap_pool_kernel<<<grid, THREADS>>>(x4, out4);
}

// round 4
// speedup vs baseline: 1.0258x; 1.0258x over previous
#include <cuda_runtime.h>
#include <cuda_bf16.h>
#include <float.h>

// DimensionAdaptivePoolingForSensors:
//   x: (B=64, w=512, h=48, M=64) f32  ->  out: (B=64, 16*6*64) f32
// Uniform bins: w-bin = w/32 (16 bins), h-bin = h/8 (6 bins).
// out[b, iw*384 + ih*64 + m] = max over 32x8 (w,h) window of x[b,w,h,m]
//
// One block per (iw, b): streams a fully contiguous 384 KB slab exactly once.
// 768 threads: thread t owns (h = t>>4, mvec = t&15) as a float4 accumulator;
// a warp reads 512 contiguous bytes per w-row -> all LDG.128, perfectly
// coalesced. Loads use .cs (streaming / evict-first) since data is one-touch.
// Then an 8:1 smem reduction over h within each h-bin produces the output.

#define POOL_W 16
#define POOL_H 6
#define DIM_B  64
#define DIM_W  512
#define DIM_H  48
#define DIM_M  64
#define WIN_W  32   // DIM_W / POOL_W
#define WIN_H  8    // DIM_H / POOL_H
#define MV     (DIM_M / 4)        // 16 float4 per (b,w,h) row
#define THREADS (DIM_H * MV)      // 48 * 16 = 768

__device__ __forceinline__ float4 f4max(float4 a, float4 b) {
    return make_float4(fmaxf(a.x, b.x), fmaxf(a.y, b.y),
                       fmaxf(a.z, b.z), fmaxf(a.w, b.w));
}

__global__ __launch_bounds__(THREADS, 2)
void dap_pool_kernel(const float4* __restrict__ x4, float4* __restrict__ out4) {
    const int iw = blockIdx.x;   // 0..15
    const int b  = blockIdx.y;   // 0..63
    const int t  = threadIdx.x;  // 0..767
    const int mv = t & (MV - 1); // 0..15
    const int h  = t >> 4;       // 0..47

    // float4-unit index: b*512*48*16 + w*48*16 + h*16 + mv ; w = iw*32 + wl
    const float4* base = x4
        + (size_t)b * (DIM_W * DIM_H * MV)
        + (size_t)(iw * WIN_W) * (DIM_H * MV)
        + (size_t)h * MV + mv;

    float4 acc = make_float4(-FLT_MAX, -FLT_MAX, -FLT_MAX, -FLT_MAX);
    #pragma unroll 8
    for (int wl = 0; wl < WIN_W; ++wl) {
        acc = f4max(acc, __ldcs(base + (size_t)wl * (DIM_H * MV)));
    }

    __shared__ float4 smem[THREADS];  // [h][mv], 12 KB
    smem[t] = acc;
    __syncthreads();

    // 96 threads: (ih = 0..5, mv = 0..15) reduce 8 h-rows and write output.
    if (t < POOL_H * MV) {
        const int ih = t >> 4;
        const int m  = t & (MV - 1);
        float4 r = smem[(ih * WIN_H) * MV + m];
        #pragma unroll
        for (int j = 1; j < WIN_H; ++j)
            r = f4max(r, smem[(ih * WIN_H + j) * MV + m]);
        // out float4 index: b*1536 + iw*96 + ih*16 + m
        __stcs(out4 + (size_t)b * (POOL_W * POOL_H * MV)
                    + (size_t)iw * (POOL_H * MV)
                    + (size_t)ih * MV + m, r);
    }
}

extern "C" void kernel_launch(void* const* d_in, const int* in_sizes, int n_in,
                              void* d_out, int out_size) {
    const float4* x4  = (const float4*)d_in[0];
    float4*      out4 = (float4*)d_out;
    dim3 grid(POOL_W, DIM_B);
    dap_pool_kernel<<<grid, THREADS>>>(x4, out4);
}

// round 5
// speedup vs baseline: 1.0264x; 1.0005x over previous
#include <cuda_runtime.h>
#include <cuda_bf16.h>
#include <float.h>

// DimensionAdaptivePoolingForSensors:
//   x: (B=64, w=512, h=48, M=64) f32  ->  out: (B=64, 16*6*64) f32
// Uniform bins: w-bin = w/32 (16 bins), h-bin = h/8 (6 bins).
// out[b, iw*384 + ih*64 + m] = max over 32x8 (w,h) window of x[b,w,h,m]
//
// One block per (iw, b): streams a fully contiguous 384 KB slab exactly once.
// 768 threads: thread t owns (h = t>>4, mvec = t&15) as float4 accumulators;
// a warp reads 512 contiguous bytes per w-row -> all LDG.128.CS, perfectly
// coalesced, evict-first. w-loop fully unrolled with two independent
// accumulator chains so ptxas front-batches loads to the register budget.
// Then an 8:1 smem reduction over h within each h-bin produces the output.

#define POOL_W 16
#define POOL_H 6
#define DIM_B  64
#define DIM_W  512
#define DIM_H  48
#define DIM_M  64
#define WIN_W  32   // DIM_W / POOL_W
#define WIN_H  8    // DIM_H / POOL_H
#define MV     (DIM_M / 4)        // 16 float4 per (b,w,h) row
#define THREADS (DIM_H * MV)      // 48 * 16 = 768

__device__ __forceinline__ float4 f4max(float4 a, float4 b) {
    return make_float4(fmaxf(a.x, b.x), fmaxf(a.y, b.y),
                       fmaxf(a.z, b.z), fmaxf(a.w, b.w));
}

__global__ __launch_bounds__(THREADS, 2)
void dap_pool_kernel(const float4* __restrict__ x4, float4* __restrict__ out4) {
    const int iw = blockIdx.x;   // 0..15
    const int b  = blockIdx.y;   // 0..63
    const int t  = threadIdx.x;  // 0..767
    const int mv = t & (MV - 1); // 0..15
    const int h  = t >> 4;       // 0..47

    // float4-unit index: b*512*48*16 + w*48*16 + h*16 + mv ; w = iw*32 + wl
    const float4* base = x4
        + (size_t)b * (DIM_W * DIM_H * MV)
        + (size_t)(iw * WIN_W) * (DIM_H * MV)
        + (size_t)h * MV + mv;

    // Two independent accumulator chains over the fully unrolled w-window.
    float4 acc0 = make_float4(-FLT_MAX, -FLT_MAX, -FLT_MAX, -FLT_MAX);
    float4 acc1 = acc0;
    #pragma unroll
    for (int wl = 0; wl < WIN_W; wl += 2) {
        acc0 = f4max(acc0, __ldcs(base + (size_t)(wl    ) * (DIM_H * MV)));
        acc1 = f4max(acc1, __ldcs(base + (size_t)(wl + 1) * (DIM_H * MV)));
    }
    float4 acc = f4max(acc0, acc1);

    __shared__ float4 smem[THREADS];  // [h][mv], 12 KB
    smem[t] = acc;
    __syncthreads();

    // 96 threads: (ih = 0..5, mv = 0..15) reduce 8 h-rows and write output.
    if (t < POOL_H * MV) {
        const int ih = t >> 4;
        const int m  = t & (MV - 1);
        float4 r = smem[(ih * WIN_H) * MV + m];
        #pragma unroll
        for (int j = 1; j < WIN_H; ++j)
            r = f4max(r, smem[(ih * WIN_H + j) * MV + m]);
        // out float4 index: b*1536 + iw*96 + ih*16 + m
        __stcs(out4 + (size_t)b * (POOL_W * POOL_H * MV)
                    + (size_t)iw * (POOL_H * MV)
                    + (size_t)ih * MV + m, r);
    }
}

extern "C" void kernel_launch(void* const* d_in, const int* in_sizes, int n_in,
                              void* d_out, int out_size) {
    const float4* x4  = (const float4*)d_in[0];
    float4*      out4 = (float4*)d_out;
    dim3 grid(POOL_W, DIM_B);
    dap_pool_kernel<<<grid, THREADS>>>(x4, out4);
}